// round 4
// baseline (speedup 1.0000x reference)
#include <cuda_runtime.h>

// Problem constants
#define BB   4
#define CC   256     // output channels (C)
#define CI   128     // inner attention dim
#define NN   4096    // H*W pixels

// Scratch (static __device__ — no allocation allowed)
__device__ float g_q[BB * NN * CI];   // [b][n][ci]
__device__ float g_k[BB * CI * NN];   // [b][ci][m]  (transposed for S-phase)
__device__ float g_v[BB * NN * CC];   // [b][m][c]

// ---------------------------------------------------------------------------
// Projection: out = W @ in + bias  (1x1 conv). in: [b][Cin][N] (n contig)
// Tile: 64 n  x 128 o.  256 threads as 16(ty) x 16(tx), micro 4n x 8o.
// Column mapping: o = o0 + half*64 + tx*4 + u  (contiguous float4 per lane)
// ---------------------------------------------------------------------------
template <bool TRANS>
__device__ __forceinline__ void proj_body(const float* __restrict__ in,
                                          const float* __restrict__ W,
                                          const float* __restrict__ bias,
                                          float* __restrict__ out,
                                          int Cin, int O) {
    __shared__ float Xs[32 * 64];    // [cc][nn]
    __shared__ float Ws[32 * 132];   // [cc][oo], padded

    const int tid = threadIdx.x;
    const int ty = tid >> 4;
    const int tx = tid & 15;
    const int n0 = blockIdx.x * 64;
    const int o0 = blockIdx.y * 128;
    const int b  = blockIdx.z;
    const float* inb = in + (size_t)b * Cin * NN;

    float acc[4][8];
#pragma unroll
    for (int i = 0; i < 4; i++)
#pragma unroll
        for (int j = 0; j < 8; j++) acc[i][j] = 0.f;

    for (int c0 = 0; c0 < Cin; c0 += 32) {
#pragma unroll
        for (int t = 0; t < 8; t++) {          // 32*64 = 2048 elems
            int e = tid + t * 256;
            int cc = e >> 6, nn = e & 63;
            Xs[cc * 64 + nn] = inb[(size_t)(c0 + cc) * NN + n0 + nn];
        }
#pragma unroll
        for (int t = 0; t < 16; t++) {         // 128*32 = 4096 elems
            int e = tid + t * 256;
            int oo = e >> 5, cc = e & 31;
            Ws[cc * 132 + oo] = W[(size_t)(o0 + oo) * Cin + c0 + cc];
        }
        __syncthreads();

#pragma unroll 4
        for (int cc = 0; cc < 32; cc++) {
            float4 w0 = *(const float4*)&Ws[cc * 132 + tx * 4];
            float4 w1 = *(const float4*)&Ws[cc * 132 + 64 + tx * 4];
#pragma unroll
            for (int i = 0; i < 4; i++) {
                float a = Xs[cc * 64 + ty * 4 + i];
                acc[i][0] += a * w0.x; acc[i][1] += a * w0.y;
                acc[i][2] += a * w0.z; acc[i][3] += a * w0.w;
                acc[i][4] += a * w1.x; acc[i][5] += a * w1.y;
                acc[i][6] += a * w1.z; acc[i][7] += a * w1.w;
            }
        }
        __syncthreads();
    }

    float bj[8];
#pragma unroll
    for (int u = 0; u < 4; u++) {
        bj[u]     = bias[o0 + tx * 4 + u];
        bj[4 + u] = bias[o0 + 64 + tx * 4 + u];
    }

    if (!TRANS) {
        // out[b][n][o]
#pragma unroll
        for (int i = 0; i < 4; i++) {
            size_t base = (size_t)b * NN * O + (size_t)(n0 + ty * 4 + i) * O + o0;
            *(float4*)&out[base + tx * 4] =
                make_float4(acc[i][0] + bj[0], acc[i][1] + bj[1],
                            acc[i][2] + bj[2], acc[i][3] + bj[3]);
            *(float4*)&out[base + 64 + tx * 4] =
                make_float4(acc[i][4] + bj[4], acc[i][5] + bj[5],
                            acc[i][6] + bj[6], acc[i][7] + bj[7]);
        }
    } else {
        // out[b][o][n]
#pragma unroll
        for (int half = 0; half < 2; half++)
#pragma unroll
            for (int u = 0; u < 4; u++) {
                int o = o0 + half * 64 + tx * 4 + u;
                float bb = bj[half * 4 + u];
                *(float4*)&out[(size_t)b * O * NN + (size_t)o * NN + n0 + ty * 4] =
                    make_float4(acc[0][half * 4 + u] + bb, acc[1][half * 4 + u] + bb,
                                acc[2][half * 4 + u] + bb, acc[3][half * 4 + u] + bb);
            }
    }
}

__global__ __launch_bounds__(256) void proj_q_kernel(const float* __restrict__ x,
                                                     const float* __restrict__ W,
                                                     const float* __restrict__ b) {
    proj_body<false>(x, W, b, g_q, 256, 128);
}
__global__ __launch_bounds__(256) void proj_k_kernel(const float* __restrict__ z,
                                                     const float* __restrict__ W,
                                                     const float* __restrict__ b) {
    proj_body<true>(z, W, b, g_k, 256, 128);
}
__global__ __launch_bounds__(256) void proj_v_kernel(const float* __restrict__ z,
                                                     const float* __restrict__ W,
                                                     const float* __restrict__ b) {
    proj_body<false>(z, W, b, g_v, 256, 256);
}

// ---------------------------------------------------------------------------
// Fused attention: per block = one batch b and 64 query rows (n0..n0+63).
// Online softmax over m chunks of 128.  O accumulator [64 n][256 c] in regs.
// ---------------------------------------------------------------------------
#define QS_F  (64 * 132)
#define KS_F  (128 * 128)
#define PS_F  (64 * 132)
#define VS_F  (64 * 256)
#define ATTN_SMEM_FLOATS (QS_F + KS_F + PS_F + VS_F + 3 * 64)
#define ATTN_SMEM_BYTES  (ATTN_SMEM_FLOATS * 4)

__global__ __launch_bounds__(256, 1)
void attn_kernel(const float* __restrict__ x_main,
                 const float* __restrict__ gamma_p,
                 float* __restrict__ out) {
    extern __shared__ float smf[];
    float* Qs  = smf;                 // [64][132]
    float* Ks  = Qs + QS_F;           // [128 k][128 m]
    float* Ps  = Ks + KS_F;           // [64][132]
    float* Vs  = Ps + PS_F;           // [64 m][256 c]
    float* m_s = Vs + VS_F;
    float* l_s = m_s + 64;
    float* a_s = l_s + 64;

    const int tid = threadIdx.x;
    const int ty = tid >> 4;
    const int tx = tid & 15;
    const int n0 = blockIdx.x * 64;
    const int b  = blockIdx.y;

    const float* qg = g_q + ((size_t)b * NN + n0) * CI;
    const float* kg = g_k + (size_t)b * CI * NN;
    const float* vg = g_v + (size_t)b * NN * CC;

    float o_acc[4][16];
#pragma unroll
    for (int i = 0; i < 4; i++)
#pragma unroll
        for (int j = 0; j < 16; j++) o_acc[i][j] = 0.f;

    // Load Q tile [64][128]
#pragma unroll
    for (int t = 0; t < 32; t++) {
        int e = tid + t * 256;
        int nn = e >> 7, kk = e & 127;
        Qs[nn * 132 + kk] = qg[(size_t)nn * CI + kk];
    }
    if (tid < 64) { m_s[tid] = -1e30f; l_s[tid] = 0.f; }
    __syncthreads();

    for (int m0 = 0; m0 < NN; m0 += 128) {
        // ---- load K chunk [128 k][128 m] ----
#pragma unroll
        for (int t = 0; t < 16; t++) {
            int e = tid + t * 256;
            int kk = e >> 5, mq = (e & 31) << 2;
            *(float4*)&Ks[kk * 128 + mq] =
                *(const float4*)&kg[(size_t)kk * NN + m0 + mq];
        }
        __syncthreads();

        // ---- S = Q K^T  (micro 4n x 8m; cols: half*64 + tx*4 + u) ----
        float s[4][8];
#pragma unroll
        for (int i = 0; i < 4; i++)
#pragma unroll
            for (int j = 0; j < 8; j++) s[i][j] = 0.f;

#pragma unroll 4
        for (int kk = 0; kk < 128; kk++) {
            float4 b0 = *(const float4*)&Ks[kk * 128 + tx * 4];
            float4 b1 = *(const float4*)&Ks[kk * 128 + 64 + tx * 4];
#pragma unroll
            for (int i = 0; i < 4; i++) {
                float a = Qs[(ty * 4 + i) * 132 + kk];
                s[i][0] += a * b0.x; s[i][1] += a * b0.y;
                s[i][2] += a * b0.z; s[i][3] += a * b0.w;
                s[i][4] += a * b1.x; s[i][5] += a * b1.y;
                s[i][6] += a * b1.z; s[i][7] += a * b1.w;
            }
        }
#pragma unroll
        for (int i = 0; i < 4; i++) {
            *(float4*)&Ps[(ty * 4 + i) * 132 + tx * 4] =
                make_float4(s[i][0], s[i][1], s[i][2], s[i][3]);
            *(float4*)&Ps[(ty * 4 + i) * 132 + 64 + tx * 4] =
                make_float4(s[i][4], s[i][5], s[i][6], s[i][7]);
        }
        __syncthreads();

        // ---- online softmax: 4 threads per row, 32 cols each ----
        {
            int r = tid >> 2, p = tid & 3;
            float* row = Ps + r * 132 + p * 32;
            float mx = -1e30f;
#pragma unroll
            for (int j = 0; j < 32; j++) mx = fmaxf(mx, row[j]);
            mx = fmaxf(mx, __shfl_xor_sync(0xffffffffu, mx, 1));
            mx = fmaxf(mx, __shfl_xor_sync(0xffffffffu, mx, 2));
            float mo = m_s[r];
            float mn = fmaxf(mo, mx);
            float sum = 0.f;
#pragma unroll
            for (int j = 0; j < 32; j++) {
                float ev = __expf(row[j] - mn);
                row[j] = ev;
                sum += ev;
            }
            sum += __shfl_xor_sync(0xffffffffu, sum, 1);
            sum += __shfl_xor_sync(0xffffffffu, sum, 2);
            if (p == 0) {
                float al = __expf(mo - mn);
                a_s[r] = al;
                l_s[r] = l_s[r] * al + sum;
                m_s[r] = mn;
            }
        }
        __syncthreads();

        // ---- rescale accumulator ----
#pragma unroll
        for (int i = 0; i < 4; i++) {
            float al = a_s[ty * 4 + i];
#pragma unroll
            for (int j = 0; j < 16; j++) o_acc[i][j] *= al;
        }

        // ---- O += P V  in two 64-row V halves ----
#pragma unroll
        for (int h = 0; h < 2; h++) {
#pragma unroll
            for (int t = 0; t < 16; t++) {
                int e = tid + t * 256;
                int mm = e >> 6, cq = (e & 63) << 2;
                *(float4*)&Vs[mm * 256 + cq] =
                    *(const float4*)&vg[(size_t)(m0 + h * 64 + mm) * CC + cq];
            }
            __syncthreads();

#pragma unroll 2
            for (int mm = 0; mm < 64; mm++) {
                float a0 = Ps[(ty * 4 + 0) * 132 + h * 64 + mm];
                float a1 = Ps[(ty * 4 + 1) * 132 + h * 64 + mm];
                float a2 = Ps[(ty * 4 + 2) * 132 + h * 64 + mm];
                float a3 = Ps[(ty * 4 + 3) * 132 + h * 64 + mm];
#pragma unroll
                for (int q = 0; q < 4; q++) {
                    float4 v = *(const float4*)&Vs[mm * 256 + q * 64 + tx * 4];
                    o_acc[0][q * 4 + 0] += a0 * v.x; o_acc[0][q * 4 + 1] += a0 * v.y;
                    o_acc[0][q * 4 + 2] += a0 * v.z; o_acc[0][q * 4 + 3] += a0 * v.w;
                    o_acc[1][q * 4 + 0] += a1 * v.x; o_acc[1][q * 4 + 1] += a1 * v.y;
                    o_acc[1][q * 4 + 2] += a1 * v.z; o_acc[1][q * 4 + 3] += a1 * v.w;
                    o_acc[2][q * 4 + 0] += a2 * v.x; o_acc[2][q * 4 + 1] += a2 * v.y;
                    o_acc[2][q * 4 + 2] += a2 * v.z; o_acc[2][q * 4 + 3] += a2 * v.w;
                    o_acc[3][q * 4 + 0] += a3 * v.x; o_acc[3][q * 4 + 1] += a3 * v.y;
                    o_acc[3][q * 4 + 2] += a3 * v.z; o_acc[3][q * 4 + 3] += a3 * v.w;
                }
            }
            __syncthreads();
        }
    }

    // ---- epilogue: out[b][c][n] = gamma * O[n][c]/l[n] + x_main[b][c][n] ----
    const float gma = gamma_p[0];
    float inv_l[4];
#pragma unroll
    for (int i = 0; i < 4; i++) inv_l[i] = 1.0f / l_s[ty * 4 + i];

    float* Ts = smf;  // reuse Qs region: [64 c][65]
    const float* xb = x_main + (size_t)b * CC * NN;
    float* ob = out + (size_t)b * CC * NN;

#pragma unroll
    for (int q = 0; q < 4; q++) {
        __syncthreads();
#pragma unroll
        for (int u = 0; u < 4; u++)
#pragma unroll
            for (int i = 0; i < 4; i++)
                Ts[(tx * 4 + u) * 65 + ty * 4 + i] = o_acc[i][q * 4 + u] * inv_l[i];
        __syncthreads();
#pragma unroll
        for (int t = 0; t < 16; t++) {
            int e = tid + t * 256;
            int cl = e >> 6, nl = e & 63;
            size_t gi = (size_t)(q * 64 + cl) * NN + n0 + nl;
            ob[gi] = gma * Ts[cl * 65 + nl] + xb[gi];
        }
    }
}

// ---------------------------------------------------------------------------
extern "C" void kernel_launch(void* const* d_in, const int* in_sizes, int n_in,
                              void* d_out, int out_size) {
    const float* x  = (const float*)d_in[0];
    const float* z  = (const float*)d_in[1];
    const float* Wq = (const float*)d_in[2];
    const float* bq = (const float*)d_in[3];
    const float* Wk = (const float*)d_in[4];
    const float* bk = (const float*)d_in[5];
    const float* Wv = (const float*)d_in[6];
    const float* bv = (const float*)d_in[7];
    const float* ga = (const float*)d_in[8];
    float* out = (float*)d_out;

    cudaFuncSetAttribute(attn_kernel, cudaFuncAttributeMaxDynamicSharedMemorySize,
                         ATTN_SMEM_BYTES);

    dim3 blk(256);
    proj_q_kernel<<<dim3(64, 1, BB), blk>>>(x, Wq, bq);
    proj_k_kernel<<<dim3(64, 1, BB), blk>>>(z, Wk, bk);
    proj_v_kernel<<<dim3(64, 2, BB), blk>>>(z, Wv, bv);
    attn_kernel<<<dim3(NN / 64, BB), blk, ATTN_SMEM_BYTES>>>(x, ga, out);
}